// round 9
// baseline (speedup 1.0000x reference)
#include <cuda_runtime.h>
#include <math.h>

// Problem constants
#define Bsz  32
#define Tlen 1024
#define Dd   512
#define Hh   512
#define NG   1536   // 3*H
#define C4H  2048   // 4*H

// -------- device scratch --------
__device__ float g_wih[Dd * NG];                 // sampled w_ih[:, :3H], [d][c]
__device__ float g_wt2[32 * 512 * 48];           // scan weights [jg][k][c], c = g*16+jl
__device__ float g_bias[C4H];
__device__ float g_xt[(size_t)4 * Tlen * 512 * 8]; // x transposed: [bg][t][k][b8]
__device__ float g_ht[2][4][512 * 8];            // ping-pong hidden, transposed [bg][k][b8]
__device__ unsigned g_bar[4 * Tlen];             // per-batch-group barrier counters

__device__ __forceinline__ float softplusf_(float x) {
    return x > 20.f ? x : log1pf(__expf(x));
}

typedef unsigned long long ull;
__device__ __forceinline__ ull pack2(float x) {
    ull d; unsigned u = __float_as_uint(x);
    asm("mov.b64 %0, {%1, %1};" : "=l"(d) : "r"(u));
    return d;
}
__device__ __forceinline__ void fma2(ull& d, ull a, ull b) {
    asm("fma.rn.f32x2 %0, %1, %2, %0;" : "+l"(d) : "l"(a), "l"(b));
}
__device__ __forceinline__ ull add2(ull a, ull b) {
    ull d;
    asm("add.rn.f32x2 %0, %1, %2;" : "=l"(d) : "l"(a), "l"(b));
    return d;
}

// ---------------- prologue: sample weights + reset barriers ----------------
__global__ void sample_all_kernel(const float* __restrict__ wih_mu, const float* __restrict__ wih_rho,
                                  const float* __restrict__ eps_ih,
                                  const float* __restrict__ whh_mu, const float* __restrict__ whh_rho,
                                  const float* __restrict__ eps_hh,
                                  const float* __restrict__ b_mu, const float* __restrict__ b_rho,
                                  const float* __restrict__ eps_b) {
    int i = blockIdx.x * blockDim.x + threadIdx.x;
    const int N1 = Dd * NG;
    const int N2 = N1 + 32 * 512 * 48;
    const int N3 = N2 + C4H;
    const int N4 = N3 + 4 * Tlen;
    if (i < N1) {
        int d = i / NG, c = i % NG;
        int s = d * C4H + c;
        g_wih[i] = wih_mu[s] + softplusf_(wih_rho[s]) * eps_ih[s];
    } else if (i < N2) {
        int jj = i - N1;
        int jg = jj / 24576;
        int r = jj % 24576;
        int k = r / 48;
        int c = r % 48;
        int g = c >> 4;
        int jl = c & 15;
        int colH = (g < 2) ? (g * 512 + jg * 16 + jl) : (1536 + jg * 16 + jl);
        int s = k * C4H + colH;
        g_wt2[jj] = whh_mu[s] + softplusf_(whh_rho[s]) * eps_hh[s];
    } else if (i < N3) {
        int jj = i - N2;
        g_bias[jj] = b_mu[jj] + softplusf_(b_rho[jj]) * eps_b[jj];
    } else if (i < N4) {
        g_bar[i - N3] = 0u;
    }
}

// ---------------- x transpose: x[b][t][d] -> xT[bg][t][k][b8] ----------------
__global__ __launch_bounds__(256) void xpose_kernel(const float* __restrict__ x) {
    int idx = blockIdx.x * 256 + threadIdx.x;      // 4*1024*128*8 = 4194304
    int b8 = idx & 7;
    int k4 = (idx >> 3) & 127;
    int t  = (idx >> 10) & 1023;
    int bg = idx >> 20;
    float4 v = *(const float4*)&x[((size_t)(bg * 8 + b8) * 1024 + t) * 512 + k4 * 4];
    size_t base = ((size_t)(bg * 1024 + t) * 512) * 8;
    g_xt[base + (size_t)(k4 * 4 + 0) * 8 + b8] = v.x;
    g_xt[base + (size_t)(k4 * 4 + 1) * 8 + b8] = v.y;
    g_xt[base + (size_t)(k4 * 4 + 2) * 8 + b8] = v.z;
    g_xt[base + (size_t)(k4 * 4 + 3) * 8 + b8] = v.w;
}

// ---------------- fused persistent GRU scan + input GEMM ----------------
#define SK_W 52

struct ScanSmem {
    float w[512 * SK_W];          // 106496 B
    float h[512 * 8];             // 16384 B, [k][b8]
    float x[2][512 * 8];          // 32768 B, [k][b8]
    float part[8 * 16 * 3 * 10];  // 15360 B (scan partials)
    float part2[8 * 16 * 3 * 10]; // 15360 B (gemm partials)
};

__global__ __launch_bounds__(256, 1) void scan_kernel(const float* __restrict__ h0,
                                                      float* __restrict__ out,
                                                      int write_last) {
    extern __shared__ float smem_raw[];
    ScanSmem* S = (ScanSmem*)smem_raw;

    const int tid = threadIdx.x;
    const int bg = blockIdx.x >> 5;
    const int jg = blockIdx.x & 31;
    const int j = tid & 15;
    const int ks = tid >> 4;
    const int k0 = ks * 32;
    const int wid = tid >> 5;
    const int lane = tid & 31;
    const int fb = tid >> 4;       // final-stage b (tid<128)
    const int jgl = jg * 16 + j;

    // ---- w_hh columns into smem ----
    {
        const float* wb = g_wt2 + (size_t)jg * 24576;
        for (int q = tid; q < 6144; q += 256) {
            int k = q / 12, c4 = (q % 12) * 4;
            float4 v = *(const float4*)&wb[k * 48 + c4];
            *(float4*)&S->w[k * SK_W + c4] = v;
        }
    }
    // ---- w_ih slice into registers (constant for whole scan) ----
    float wr_ih[32], wz_ih[32], wn_ih[32];
    {
        const float* p = g_wih + (size_t)k0 * NG + (jg * 16 + j);
#pragma unroll
        for (int kk = 0; kk < 32; kk++) {
            wr_ih[kk] = __ldg(&p[kk * NG]);
            wz_ih[kk] = __ldg(&p[kk * NG + 512]);
            wn_ih[kk] = __ldg(&p[kk * NG + 1024]);
        }
    }
    float b_r = 0.f, b_z = 0.f, b_n = 0.f, b_hn = 0.f;
    if (tid < 128) {
        b_r  = g_bias[jgl];
        b_z  = g_bias[512 + jgl];
        b_n  = g_bias[1024 + jgl];
        b_hn = g_bias[1536 + jgl];
    }

    // ---- stage x(0) into xbuf[1] (temp) ----
    {
        const float* xsrc = g_xt + ((size_t)(bg * 1024 + 0) * 512) * 8;
#pragma unroll
        for (int i = 0; i < 4; i++) {
            int q = (tid + 256 * i) << 2;
            float4 v = __ldg((const float4*)&xsrc[q]);
            *(float4*)&S->x[1][q] = v;
        }
    }
    __syncthreads();

    // ---- compute xg(0) into regs ----
    float xr = 0.f, xz = 0.f, xn = 0.f;
    {
        ull acc[3][4];
#pragma unroll
        for (int g = 0; g < 3; g++)
#pragma unroll
            for (int p = 0; p < 4; p++) acc[g][p] = 0ull;
        const float* xp = &S->x[1][0];
#pragma unroll
        for (int kk = 0; kk < 32; kk++) {
            int k = k0 + kk;
            ulonglong2 hA = *(const ulonglong2*)&xp[k * 8];
            ulonglong2 hB = *(const ulonglong2*)&xp[k * 8 + 4];
            ull wr = pack2(wr_ih[kk]);
            ull wz = pack2(wz_ih[kk]);
            ull wn = pack2(wn_ih[kk]);
            fma2(acc[0][0], hA.x, wr); fma2(acc[0][1], hA.y, wr);
            fma2(acc[0][2], hB.x, wr); fma2(acc[0][3], hB.y, wr);
            fma2(acc[1][0], hA.x, wz); fma2(acc[1][1], hA.y, wz);
            fma2(acc[1][2], hB.x, wz); fma2(acc[1][3], hB.y, wz);
            fma2(acc[2][0], hA.x, wn); fma2(acc[2][1], hA.y, wn);
            fma2(acc[2][2], hB.x, wn); fma2(acc[2][3], hB.y, wn);
        }
#pragma unroll
        for (int g = 0; g < 3; g++)
#pragma unroll
            for (int p = 0; p < 4; p++) {
                ull o = __shfl_xor_sync(0xffffffffu, acc[g][p], 16);
                acc[g][p] = add2(acc[g][p], o);
            }
        if (lane < 16) {
#pragma unroll
            for (int g = 0; g < 3; g++)
#pragma unroll
                for (int p = 0; p < 4; p++)
                    *(ull*)&S->part[(((wid * 16 + j) * 3 + g) * 5 + p) * 2] = acc[g][p];
        }
        __syncthreads();
        if (tid < 128) {
#pragma unroll
            for (int w = 0; w < 8; w++) {
                const float* pp = &S->part[((w * 16 + j) * 3) * 10 + fb];
                xr += pp[0];
                xz += pp[10];
                xn += pp[20];
            }
        }
    }

    // ---- stage x(1) into xbuf[0]; load h0 into S->h ----
    {
        const float* xsrc = g_xt + ((size_t)(bg * 1024 + 1) * 512) * 8;
#pragma unroll
        for (int i = 0; i < 4; i++) {
            int q = (tid + 256 * i) << 2;
            float4 v = __ldg((const float4*)&xsrc[q]);
            *(float4*)&S->x[0][q] = v;
        }
        const float* hsrc = h0 + (size_t)bg * 8 * 512;
        for (int q = tid; q < 1024; q += 256) {
            int b8 = q >> 7, kq = (q & 127) << 2;
            float4 v = *(const float4*)&hsrc[b8 * 512 + kq];
            S->h[(kq + 0) * 8 + b8] = v.x;
            S->h[(kq + 1) * 8 + b8] = v.y;
            S->h[(kq + 2) * 8 + b8] = v.z;
            S->h[(kq + 3) * 8 + b8] = v.w;
        }
    }
    __syncthreads();

    for (int t = 0; t < Tlen; t++) {
        const bool more = (t < Tlen - 1);
        const bool havex = (t + 2 < Tlen);
        // issue LDG for x(t+2) early
        float4 x4[4];
        if (havex) {
            const float* xsrc = g_xt + ((size_t)(bg * 1024 + t + 2) * 512) * 8;
#pragma unroll
            for (int i = 0; i < 4; i++)
                x4[i] = __ldg((const float4*)&xsrc[(tid + 256 * i) << 2]);
        }

        // ---- gemm dots for xg(t+1) (independent of h(t)) ----
        if (more) {
            ull acc2[3][4];
#pragma unroll
            for (int g = 0; g < 3; g++)
#pragma unroll
                for (int p = 0; p < 4; p++) acc2[g][p] = 0ull;
            const float* xp = &S->x[t & 1][0];
#pragma unroll
            for (int kk = 0; kk < 32; kk++) {
                int k = k0 + kk;
                ulonglong2 hA = *(const ulonglong2*)&xp[k * 8];
                ulonglong2 hB = *(const ulonglong2*)&xp[k * 8 + 4];
                ull wr = pack2(wr_ih[kk]);
                ull wz = pack2(wz_ih[kk]);
                ull wn = pack2(wn_ih[kk]);
                fma2(acc2[0][0], hA.x, wr); fma2(acc2[0][1], hA.y, wr);
                fma2(acc2[0][2], hB.x, wr); fma2(acc2[0][3], hB.y, wr);
                fma2(acc2[1][0], hA.x, wz); fma2(acc2[1][1], hA.y, wz);
                fma2(acc2[1][2], hB.x, wz); fma2(acc2[1][3], hB.y, wz);
                fma2(acc2[2][0], hA.x, wn); fma2(acc2[2][1], hA.y, wn);
                fma2(acc2[2][2], hB.x, wn); fma2(acc2[2][3], hB.y, wn);
            }
#pragma unroll
            for (int g = 0; g < 3; g++)
#pragma unroll
                for (int p = 0; p < 4; p++) {
                    ull o = __shfl_xor_sync(0xffffffffu, acc2[g][p], 16);
                    acc2[g][p] = add2(acc2[g][p], o);
                }
            if (lane < 16) {
#pragma unroll
                for (int g = 0; g < 3; g++)
#pragma unroll
                    for (int p = 0; p < 4; p++)
                        *(ull*)&S->part2[(((wid * 16 + j) * 3 + g) * 5 + p) * 2] = acc2[g][p];
            }
        }

        // ---- scan dots: h(t) @ w_hh ----
        {
            ull acc[3][4];
#pragma unroll
            for (int g = 0; g < 3; g++)
#pragma unroll
                for (int p = 0; p < 4; p++) acc[g][p] = 0ull;
#pragma unroll 4
            for (int kk = 0; kk < 32; kk++) {
                int k = k0 + kk;
                const float* hp = &S->h[k * 8];
                ulonglong2 hA = *(const ulonglong2*)(hp);
                ulonglong2 hB = *(const ulonglong2*)(hp + 4);
                const float* wp = &S->w[k * SK_W];
                ull wr = pack2(wp[j]);
                ull wz = pack2(wp[16 + j]);
                ull wn = pack2(wp[32 + j]);
                fma2(acc[0][0], hA.x, wr); fma2(acc[0][1], hA.y, wr);
                fma2(acc[0][2], hB.x, wr); fma2(acc[0][3], hB.y, wr);
                fma2(acc[1][0], hA.x, wz); fma2(acc[1][1], hA.y, wz);
                fma2(acc[1][2], hB.x, wz); fma2(acc[1][3], hB.y, wz);
                fma2(acc[2][0], hA.x, wn); fma2(acc[2][1], hA.y, wn);
                fma2(acc[2][2], hB.x, wn); fma2(acc[2][3], hB.y, wn);
            }
#pragma unroll
            for (int g = 0; g < 3; g++)
#pragma unroll
                for (int p = 0; p < 4; p++) {
                    ull o = __shfl_xor_sync(0xffffffffu, acc[g][p], 16);
                    acc[g][p] = add2(acc[g][p], o);
                }
            if (lane < 16) {
#pragma unroll
                for (int g = 0; g < 3; g++)
#pragma unroll
                    for (int p = 0; p < 4; p++)
                        *(ull*)&S->part[(((wid * 16 + j) * 3 + g) * 5 + p) * 2] = acc[g][p];
            }
        }
        __syncthreads();   // A

        // ---- final: reduce scan partials + gates + h store ----
        float hnew = 0.f;
        if (tid < 128) {
            float sr = 0.f, sz = 0.f, sn = 0.f;
#pragma unroll
            for (int w = 0; w < 8; w++) {
                const float* pp = &S->part[((w * 16 + j) * 3) * 10 + fb];
                sr += pp[0];
                sz += pp[10];
                sn += pp[20];
            }
            float r = 1.f / (1.f + __expf(-(sr + xr + b_r)));
            float z = 1.f / (1.f + __expf(-(sz + xz + b_z)));
            float n = tanhf(xn + b_n + r * (sn + b_hn));
            float hprev = S->h[jgl * 8 + fb];
            hnew = (1.f - z) * n + z * hprev;
            if (more) g_ht[(t + 1) & 1][bg][jgl * 8 + fb] = hnew;
        }
        // stage x(t+2) into other buffer (gemm of this step already read S->x[t&1])
        if (havex) {
#pragma unroll
            for (int i = 0; i < 4; i++)
                *(float4*)&S->x[(t + 1) & 1][(tid + 256 * i) << 2] = x4[i];
        }
        __syncthreads();   // B: h stores + part2 consumers ordered

        if (more) {
            if (tid == 0) {
                unsigned* bp = &g_bar[bg * Tlen + t];
                asm volatile("red.release.gpu.global.add.u32 [%0], %1;"
                             :: "l"(bp), "r"(1u) : "memory");
            }
            // ---- barrier shadow: out STG + gemm reduce for xg(t+1) ----
            if (tid < 128) {
                out[((size_t)(bg * 8 + fb) * 1024 + t) * 512 + jgl] = hnew;
                xr = 0.f; xz = 0.f; xn = 0.f;
#pragma unroll
                for (int w = 0; w < 8; w++) {
                    const float* pp = &S->part2[((w * 16 + j) * 3) * 10 + fb];
                    xr += pp[0];
                    xz += pp[10];
                    xn += pp[20];
                }
            }
            if (tid == 0) {
                unsigned* bp = &g_bar[bg * Tlen + t];
                unsigned vv;
                do {
                    asm volatile("ld.acquire.gpu.global.u32 %0, [%1];"
                                 : "=r"(vv) : "l"(bp) : "memory");
                } while (vv < 32u);
            }
            __syncthreads();   // D

            // ---- pull h(t+1) ----
            const float* hsrc = &g_ht[(t + 1) & 1][bg][0];
#pragma unroll
            for (int i = 0; i < 4; i++) {
                int q = (tid + 256 * i) << 2;
                float4 v = __ldcg((const float4*)&hsrc[q]);
                *(float4*)&S->h[q] = v;
            }
            __syncthreads();   // E
        } else {
            if (tid < 128) {
                out[((size_t)(bg * 8 + fb) * 1024 + t) * 512 + jgl] = hnew;
                if (write_last)
                    out[(size_t)Bsz * Tlen * Hh + (bg * 8 + fb) * 512 + jgl] = hnew;
            }
        }
    }
}

// ---------------- launch ----------------
extern "C" void kernel_launch(void* const* d_in, const int* in_sizes, int n_in,
                              void* d_out, int out_size) {
    const float* x       = (const float*)d_in[0];
    const float* h0      = (const float*)d_in[1];
    const float* wih_mu  = (const float*)d_in[2];
    const float* wih_rho = (const float*)d_in[3];
    const float* whh_mu  = (const float*)d_in[4];
    const float* whh_rho = (const float*)d_in[5];
    const float* b_mu    = (const float*)d_in[6];
    const float* b_rho   = (const float*)d_in[7];
    const float* eps_ih  = (const float*)d_in[8];
    const float* eps_hh  = (const float*)d_in[9];
    const float* eps_b   = (const float*)d_in[10];
    float* out = (float*)d_out;

    {
        int total = Dd * NG + 32 * 512 * 48 + C4H + 4 * Tlen;
        int blocks = (total + 255) / 256;
        sample_all_kernel<<<blocks, 256>>>(wih_mu, wih_rho, eps_ih,
                                           whh_mu, whh_rho, eps_hh,
                                           b_mu, b_rho, eps_b);
    }
    {
        int threads = 4 * 1024 * 128 * 8;   // 4194304
        xpose_kernel<<<threads / 256, 256>>>(x);
    }
    {
        int smem = (int)sizeof(ScanSmem);
        cudaFuncSetAttribute(scan_kernel, cudaFuncAttributeMaxDynamicSharedMemorySize, smem);
        int write_last = (out_size >= Bsz * Tlen * Hh + Bsz * Hh) ? 1 : 0;
        scan_kernel<<<128, 256, smem>>>(h0, out, write_last);
    }
}

// round 10
// speedup vs baseline: 1.5077x; 1.5077x over previous
#include <cuda_runtime.h>
#include <math.h>

// Problem constants
#define Bsz  32
#define Tlen 1024
#define Dd   512
#define Hh   512
#define NG   1536   // 3*H
#define C4H  2048   // 4*H

// -------- device scratch --------
__device__ float g_wih[Dd * NG];                 // sampled w_ih[:, :3H], [d][c]
__device__ float g_wt2[64 * 512 * 24];           // scan weights [jg64][k][c], c = g*8+jl
__device__ float g_bias[C4H];
__device__ float g_xt[(size_t)4 * Tlen * 512 * 8]; // x transposed: [bg][t][k][b8]
__device__ float g_ht[2][4][512 * 8];            // ping-pong hidden, transposed [bg][k][b8]
__device__ unsigned g_bar[4 * Tlen];             // per-batch-group barrier counters

__device__ __forceinline__ float softplusf_(float x) {
    return x > 20.f ? x : log1pf(__expf(x));
}

typedef unsigned long long ull;
__device__ __forceinline__ ull pack2(float x) {
    ull d; unsigned u = __float_as_uint(x);
    asm("mov.b64 %0, {%1, %1};" : "=l"(d) : "r"(u));
    return d;
}
__device__ __forceinline__ void fma2(ull& d, ull a, ull b) {
    asm("fma.rn.f32x2 %0, %1, %2, %0;" : "+l"(d) : "l"(a), "l"(b));
}
__device__ __forceinline__ ull add2(ull a, ull b) {
    ull d;
    asm("add.rn.f32x2 %0, %1, %2;" : "=l"(d) : "l"(a), "l"(b));
    return d;
}

// ---------------- prologue: sample weights + reset barriers ----------------
__global__ void sample_all_kernel(const float* __restrict__ wih_mu, const float* __restrict__ wih_rho,
                                  const float* __restrict__ eps_ih,
                                  const float* __restrict__ whh_mu, const float* __restrict__ whh_rho,
                                  const float* __restrict__ eps_hh,
                                  const float* __restrict__ b_mu, const float* __restrict__ b_rho,
                                  const float* __restrict__ eps_b) {
    int i = blockIdx.x * blockDim.x + threadIdx.x;
    const int N1 = Dd * NG;
    const int N2 = N1 + 64 * 512 * 24;
    const int N3 = N2 + C4H;
    const int N4 = N3 + 4 * Tlen;
    if (i < N1) {
        int d = i / NG, c = i % NG;
        int s = d * C4H + c;
        g_wih[i] = wih_mu[s] + softplusf_(wih_rho[s]) * eps_ih[s];
    } else if (i < N2) {
        int jj = i - N1;
        int jg = jj / 12288;           // 64 groups
        int r = jj % 12288;
        int k = r / 24;
        int c = r % 24;
        int g = c >> 3;
        int jl = c & 7;
        int colH = (g < 2) ? (g * 512 + jg * 8 + jl) : (1536 + jg * 8 + jl);
        int s = k * C4H + colH;
        g_wt2[jj] = whh_mu[s] + softplusf_(whh_rho[s]) * eps_hh[s];
    } else if (i < N3) {
        int jj = i - N2;
        g_bias[jj] = b_mu[jj] + softplusf_(b_rho[jj]) * eps_b[jj];
    } else if (i < N4) {
        g_bar[i - N3] = 0u;
    }
}

// ---------------- x transpose: x[b][t][d] -> xT[bg][t][k][b8] ----------------
__global__ __launch_bounds__(256) void xpose_kernel(const float* __restrict__ x) {
    int idx = blockIdx.x * 256 + threadIdx.x;      // 4*1024*128*8 = 4194304
    int b8 = idx & 7;
    int k4 = (idx >> 3) & 127;
    int t  = (idx >> 10) & 1023;
    int bg = idx >> 20;
    float4 v = *(const float4*)&x[((size_t)(bg * 8 + b8) * 1024 + t) * 512 + k4 * 4];
    size_t base = ((size_t)(bg * 1024 + t) * 512) * 8;
    g_xt[base + (size_t)(k4 * 4 + 0) * 8 + b8] = v.x;
    g_xt[base + (size_t)(k4 * 4 + 1) * 8 + b8] = v.y;
    g_xt[base + (size_t)(k4 * 4 + 2) * 8 + b8] = v.z;
    g_xt[base + (size_t)(k4 * 4 + 3) * 8 + b8] = v.w;
}

// ---------------- fused persistent GRU scan + input GEMM ----------------
// 256 CTAs = 4 bg (8 b) x 64 jg (8 j). 2 CTAs/SM for latency overlap.
#define SK_W 25

struct ScanSmem {
    float w[512 * SK_W];     // 51200 B, [k][c] c=g*8+jl
    float h[512 * 8];        // 16384 B, [k][b8]
    float x[2][512 * 8];     // 32768 B, [k][b8]
    float part[8 * 8 * 24];  // 6144 B  (scan partials) [w][jl][g*8+b]
    float part2[8 * 8 * 24]; // 6144 B  (gemm partials)
};                           // 112640 B total

__global__ __launch_bounds__(256, 2) void scan_kernel(const float* __restrict__ h0,
                                                      float* __restrict__ out,
                                                      int write_last) {
    extern __shared__ float smem_raw[];
    ScanSmem* S = (ScanSmem*)smem_raw;

    const int tid = threadIdx.x;
    const int bg = blockIdx.x >> 6;
    const int jg = blockIdx.x & 63;
    const int jl = tid & 7;
    const int ks = tid >> 3;       // 32 k-slices, k = kk*32 + ks
    const int wid = tid >> 5;
    const int lane = tid & 31;
    const int fb = tid >> 3;       // final-stage b (tid<64)
    const int jgl = jg * 8 + jl;

    // ---- w_hh slice into smem (stride 25, scalar stores) ----
    {
        const float* wb = g_wt2 + (size_t)jg * 12288;
        for (int q = tid; q < 3072; q += 256) {
            int k = q / 6, c4 = (q % 6) * 4;
            float4 v = *(const float4*)&wb[k * 24 + c4];
            S->w[k * SK_W + c4 + 0] = v.x;
            S->w[k * SK_W + c4 + 1] = v.y;
            S->w[k * SK_W + c4 + 2] = v.z;
            S->w[k * SK_W + c4 + 3] = v.w;
        }
    }
    // ---- w_ih slice into registers ----
    float wr_ih[16], wz_ih[16], wn_ih[16];
#pragma unroll
    for (int kk = 0; kk < 16; kk++) {
        int k = kk * 32 + ks;
        wr_ih[kk] = __ldg(&g_wih[(size_t)k * NG + jgl]);
        wz_ih[kk] = __ldg(&g_wih[(size_t)k * NG + 512 + jgl]);
        wn_ih[kk] = __ldg(&g_wih[(size_t)k * NG + 1024 + jgl]);
    }
    float b_r = 0.f, b_z = 0.f, b_n = 0.f, b_hn = 0.f;
    if (tid < 64) {
        b_r  = g_bias[jgl];
        b_z  = g_bias[512 + jgl];
        b_n  = g_bias[1024 + jgl];
        b_hn = g_bias[1536 + jgl];
    }

    // ---- stage x(0) into xbuf[1] (temp) ----
    {
        const float* xsrc = g_xt + ((size_t)(bg * 1024 + 0) * 512) * 8;
#pragma unroll
        for (int i = 0; i < 4; i++) {
            int q = (tid + 256 * i) << 2;
            float4 v = __ldg((const float4*)&xsrc[q]);
            *(float4*)&S->x[1][q] = v;
        }
    }
    __syncthreads();

    // ---- compute xg(0) ----
    float xr = 0.f, xz = 0.f, xn = 0.f;
    {
        ull acc[3][4];
#pragma unroll
        for (int g = 0; g < 3; g++)
#pragma unroll
            for (int p = 0; p < 4; p++) acc[g][p] = 0ull;
        const float* xp = &S->x[1][0];
#pragma unroll
        for (int kk = 0; kk < 16; kk++) {
            int k = kk * 32 + ks;
            ulonglong2 hA = *(const ulonglong2*)&xp[k * 8];
            ulonglong2 hB = *(const ulonglong2*)&xp[k * 8 + 4];
            ull wr = pack2(wr_ih[kk]);
            ull wz = pack2(wz_ih[kk]);
            ull wn = pack2(wn_ih[kk]);
            fma2(acc[0][0], hA.x, wr); fma2(acc[0][1], hA.y, wr);
            fma2(acc[0][2], hB.x, wr); fma2(acc[0][3], hB.y, wr);
            fma2(acc[1][0], hA.x, wz); fma2(acc[1][1], hA.y, wz);
            fma2(acc[1][2], hB.x, wz); fma2(acc[1][3], hB.y, wz);
            fma2(acc[2][0], hA.x, wn); fma2(acc[2][1], hA.y, wn);
            fma2(acc[2][2], hB.x, wn); fma2(acc[2][3], hB.y, wn);
        }
#pragma unroll
        for (int g = 0; g < 3; g++)
#pragma unroll
            for (int p = 0; p < 4; p++) {
                ull o = __shfl_xor_sync(0xffffffffu, acc[g][p], 8);
                acc[g][p] = add2(acc[g][p], o);
                o = __shfl_xor_sync(0xffffffffu, acc[g][p], 16);
                acc[g][p] = add2(acc[g][p], o);
            }
        if (lane < 8) {
#pragma unroll
            for (int g = 0; g < 3; g++)
#pragma unroll
                for (int p = 0; p < 4; p++)
                    *(ull*)&S->part[(wid * 8 + jl) * 24 + g * 8 + p * 2] = acc[g][p];
        }
        __syncthreads();
        if (tid < 64) {
#pragma unroll
            for (int w = 0; w < 8; w++) {
                const float* pp = &S->part[(w * 8 + jl) * 24];
                xr += pp[fb];
                xz += pp[8 + fb];
                xn += pp[16 + fb];
            }
        }
    }

    // ---- stage x(1) into xbuf[0]; load h0 into S->h ----
    {
        const float* xsrc = g_xt + ((size_t)(bg * 1024 + 1) * 512) * 8;
#pragma unroll
        for (int i = 0; i < 4; i++) {
            int q = (tid + 256 * i) << 2;
            float4 v = __ldg((const float4*)&xsrc[q]);
            *(float4*)&S->x[0][q] = v;
        }
        const float* hsrc = h0 + (size_t)bg * 8 * 512;
        for (int q = tid; q < 1024; q += 256) {
            int b8 = q >> 7, kq = (q & 127) << 2;
            float4 v = *(const float4*)&hsrc[b8 * 512 + kq];
            S->h[(kq + 0) * 8 + b8] = v.x;
            S->h[(kq + 1) * 8 + b8] = v.y;
            S->h[(kq + 2) * 8 + b8] = v.z;
            S->h[(kq + 3) * 8 + b8] = v.w;
        }
    }
    __syncthreads();

    for (int t = 0; t < Tlen; t++) {
        const bool more = (t < Tlen - 1);
        const bool havex = (t + 2 < Tlen);
        // issue LDG for x(t+2) early
        float4 x4[4];
        if (havex) {
            const float* xsrc = g_xt + ((size_t)(bg * 1024 + t + 2) * 512) * 8;
#pragma unroll
            for (int i = 0; i < 4; i++)
                x4[i] = __ldg((const float4*)&xsrc[(tid + 256 * i) << 2]);
        }

        // ---- scan dots: h(t) @ w_hh ----
        {
            ull acc[3][4];
#pragma unroll
            for (int g = 0; g < 3; g++)
#pragma unroll
                for (int p = 0; p < 4; p++) acc[g][p] = 0ull;
#pragma unroll 4
            for (int kk = 0; kk < 16; kk++) {
                int k = kk * 32 + ks;
                const float* hp = &S->h[k * 8];
                ulonglong2 hA = *(const ulonglong2*)(hp);
                ulonglong2 hB = *(const ulonglong2*)(hp + 4);
                const float* wp = &S->w[k * SK_W];
                ull wr = pack2(wp[jl]);
                ull wz = pack2(wp[8 + jl]);
                ull wn = pack2(wp[16 + jl]);
                fma2(acc[0][0], hA.x, wr); fma2(acc[0][1], hA.y, wr);
                fma2(acc[0][2], hB.x, wr); fma2(acc[0][3], hB.y, wr);
                fma2(acc[1][0], hA.x, wz); fma2(acc[1][1], hA.y, wz);
                fma2(acc[1][2], hB.x, wz); fma2(acc[1][3], hB.y, wz);
                fma2(acc[2][0], hA.x, wn); fma2(acc[2][1], hA.y, wn);
                fma2(acc[2][2], hB.x, wn); fma2(acc[2][3], hB.y, wn);
            }
#pragma unroll
            for (int g = 0; g < 3; g++)
#pragma unroll
                for (int p = 0; p < 4; p++) {
                    ull o = __shfl_xor_sync(0xffffffffu, acc[g][p], 8);
                    acc[g][p] = add2(acc[g][p], o);
                    o = __shfl_xor_sync(0xffffffffu, acc[g][p], 16);
                    acc[g][p] = add2(acc[g][p], o);
                }
            if (lane < 8) {
#pragma unroll
                for (int g = 0; g < 3; g++)
#pragma unroll
                    for (int p = 0; p < 4; p++)
                        *(ull*)&S->part[(wid * 8 + jl) * 24 + g * 8 + p * 2] = acc[g][p];
            }
        }
        __syncthreads();   // A

        // ---- final: reduce scan partials + gates + h store ----
        float hnew = 0.f;
        if (tid < 64) {
            float sr = 0.f, sz = 0.f, sn = 0.f;
#pragma unroll
            for (int w = 0; w < 8; w++) {
                const float* pp = &S->part[(w * 8 + jl) * 24];
                sr += pp[fb];
                sz += pp[8 + fb];
                sn += pp[16 + fb];
            }
            float r = 1.f / (1.f + __expf(-(sr + xr + b_r)));
            float z = 1.f / (1.f + __expf(-(sz + xz + b_z)));
            float n = tanhf(xn + b_n + r * (sn + b_hn));
            float hprev = S->h[jgl * 8 + fb];
            hnew = (1.f - z) * n + z * hprev;
            if (more) g_ht[(t + 1) & 1][bg][jgl * 8 + fb] = hnew;
        }
        // stage x(t+2)
        if (havex) {
#pragma unroll
            for (int i = 0; i < 4; i++)
                *(float4*)&S->x[(t + 1) & 1][(tid + 256 * i) << 2] = x4[i];
        }
        __syncthreads();   // B

        if (more) {
            if (tid == 0) {
                unsigned* bp = &g_bar[bg * Tlen + t];
                asm volatile("red.release.gpu.global.add.u32 [%0], %1;"
                             :: "l"(bp), "r"(1u) : "memory");
            }

            // ---- barrier shadow: gemm dots for xg(t+1) ----
            {
                ull acc2[3][4];
#pragma unroll
                for (int g = 0; g < 3; g++)
#pragma unroll
                    for (int p = 0; p < 4; p++) acc2[g][p] = 0ull;
                const float* xp = &S->x[t & 1][0];
#pragma unroll
                for (int kk = 0; kk < 16; kk++) {
                    int k = kk * 32 + ks;
                    ulonglong2 hA = *(const ulonglong2*)&xp[k * 8];
                    ulonglong2 hB = *(const ulonglong2*)&xp[k * 8 + 4];
                    ull wr = pack2(wr_ih[kk]);
                    ull wz = pack2(wz_ih[kk]);
                    ull wn = pack2(wn_ih[kk]);
                    fma2(acc2[0][0], hA.x, wr); fma2(acc2[0][1], hA.y, wr);
                    fma2(acc2[0][2], hB.x, wr); fma2(acc2[0][3], hB.y, wr);
                    fma2(acc2[1][0], hA.x, wz); fma2(acc2[1][1], hA.y, wz);
                    fma2(acc2[1][2], hB.x, wz); fma2(acc2[1][3], hB.y, wz);
                    fma2(acc2[2][0], hA.x, wn); fma2(acc2[2][1], hA.y, wn);
                    fma2(acc2[2][2], hB.x, wn); fma2(acc2[2][3], hB.y, wn);
                }
#pragma unroll
                for (int g = 0; g < 3; g++)
#pragma unroll
                    for (int p = 0; p < 4; p++) {
                        ull o = __shfl_xor_sync(0xffffffffu, acc2[g][p], 8);
                        acc2[g][p] = add2(acc2[g][p], o);
                        o = __shfl_xor_sync(0xffffffffu, acc2[g][p], 16);
                        acc2[g][p] = add2(acc2[g][p], o);
                    }
                if (lane < 8) {
#pragma unroll
                    for (int g = 0; g < 3; g++)
#pragma unroll
                        for (int p = 0; p < 4; p++)
                            *(ull*)&S->part2[(wid * 8 + jl) * 24 + g * 8 + p * 2] = acc2[g][p];
                }
            }
            __syncthreads();   // C
            if (tid < 64) {
                out[((size_t)(bg * 8 + fb) * 1024 + t) * 512 + jgl] = hnew;
                xr = 0.f; xz = 0.f; xn = 0.f;
#pragma unroll
                for (int w = 0; w < 8; w++) {
                    const float* pp = &S->part2[(w * 8 + jl) * 24];
                    xr += pp[fb];
                    xz += pp[8 + fb];
                    xn += pp[16 + fb];
                }
            }
            if (tid == 0) {
                unsigned* bp = &g_bar[bg * Tlen + t];
                unsigned vv;
                do {
                    asm volatile("ld.acquire.gpu.global.u32 %0, [%1];"
                                 : "=r"(vv) : "l"(bp) : "memory");
                } while (vv < 64u);
            }
            __syncthreads();   // D

            // ---- pull h(t+1) ----
            const float* hsrc = &g_ht[(t + 1) & 1][bg][0];
#pragma unroll
            for (int i = 0; i < 4; i++) {
                int q = (tid + 256 * i) << 2;
                float4 v = __ldcg((const float4*)&hsrc[q]);
                *(float4*)&S->h[q] = v;
            }
            __syncthreads();   // E
        } else {
            if (tid < 64) {
                out[((size_t)(bg * 8 + fb) * 1024 + t) * 512 + jgl] = hnew;
                if (write_last)
                    out[(size_t)Bsz * Tlen * Hh + (bg * 8 + fb) * 512 + jgl] = hnew;
            }
        }
    }
}

// ---------------- launch ----------------
extern "C" void kernel_launch(void* const* d_in, const int* in_sizes, int n_in,
                              void* d_out, int out_size) {
    const float* x       = (const float*)d_in[0];
    const float* h0      = (const float*)d_in[1];
    const float* wih_mu  = (const float*)d_in[2];
    const float* wih_rho = (const float*)d_in[3];
    const float* whh_mu  = (const float*)d_in[4];
    const float* whh_rho = (const float*)d_in[5];
    const float* b_mu    = (const float*)d_in[6];
    const float* b_rho   = (const float*)d_in[7];
    const float* eps_ih  = (const float*)d_in[8];
    const float* eps_hh  = (const float*)d_in[9];
    const float* eps_b   = (const float*)d_in[10];
    float* out = (float*)d_out;

    {
        int total = Dd * NG + 64 * 512 * 24 + C4H + 4 * Tlen;
        int blocks = (total + 255) / 256;
        sample_all_kernel<<<blocks, 256>>>(wih_mu, wih_rho, eps_ih,
                                           whh_mu, whh_rho, eps_hh,
                                           b_mu, b_rho, eps_b);
    }
    {
        int threads = 4 * 1024 * 128 * 8;   // 4194304
        xpose_kernel<<<threads / 256, 256>>>(x);
    }
    {
        int smem = (int)sizeof(ScanSmem);
        cudaFuncSetAttribute(scan_kernel, cudaFuncAttributeMaxDynamicSharedMemorySize, smem);
        int write_last = (out_size >= Bsz * Tlen * Hh + Bsz * Hh) ? 1 : 0;
        scan_kernel<<<256, 256, smem>>>(h0, out, write_last);
    }
}

// round 11
// speedup vs baseline: 1.8271x; 1.2118x over previous
#include <cuda_runtime.h>
#include <math.h>

// Problem constants
#define Bsz  32
#define Tlen 1024
#define Dd   512
#define Hh   512
#define NG   1536   // 3*H
#define C4H  2048   // 4*H

// -------- device scratch --------
__device__ float g_wih[Dd * NG];                 // sampled w_ih[:, :3H], [d][c]
__device__ float g_wt2[32 * 512 * 48];           // scan weights [jg][k][c], c = g*16+jl
__device__ float g_bias[C4H];
__device__ float g_xt[(size_t)4 * Tlen * 512 * 8]; // x transposed: [bg][t][k][b8]
__device__ float g_ht[2][4][512 * 8];            // ping-pong hidden, transposed [bg][k][b8]
__device__ unsigned g_bar[4 * Tlen];             // per-batch-group barrier counters

__device__ __forceinline__ float softplusf_(float x) {
    return x > 20.f ? x : log1pf(__expf(x));
}

typedef unsigned long long ull;
__device__ __forceinline__ ull pack2(float x) {
    ull d; unsigned u = __float_as_uint(x);
    asm("mov.b64 %0, {%1, %1};" : "=l"(d) : "r"(u));
    return d;
}
__device__ __forceinline__ void fma2(ull& d, ull a, ull b) {
    asm("fma.rn.f32x2 %0, %1, %2, %0;" : "+l"(d) : "l"(a), "l"(b));
}
__device__ __forceinline__ ull add2(ull a, ull b) {
    ull d;
    asm("add.rn.f32x2 %0, %1, %2;" : "=l"(d) : "l"(a), "l"(b));
    return d;
}

// ---------------- prologue: sample weights + reset barriers ----------------
__global__ void sample_all_kernel(const float* __restrict__ wih_mu, const float* __restrict__ wih_rho,
                                  const float* __restrict__ eps_ih,
                                  const float* __restrict__ whh_mu, const float* __restrict__ whh_rho,
                                  const float* __restrict__ eps_hh,
                                  const float* __restrict__ b_mu, const float* __restrict__ b_rho,
                                  const float* __restrict__ eps_b) {
    int i = blockIdx.x * blockDim.x + threadIdx.x;
    const int N1 = Dd * NG;
    const int N2 = N1 + 32 * 512 * 48;
    const int N3 = N2 + C4H;
    const int N4 = N3 + 4 * Tlen;
    if (i < N1) {
        int d = i / NG, c = i % NG;
        int s = d * C4H + c;
        g_wih[i] = wih_mu[s] + softplusf_(wih_rho[s]) * eps_ih[s];
    } else if (i < N2) {
        int jj = i - N1;
        int jg = jj / 24576;
        int r = jj % 24576;
        int k = r / 48;
        int c = r % 48;
        int g = c >> 4;
        int jl = c & 15;
        int colH = (g < 2) ? (g * 512 + jg * 16 + jl) : (1536 + jg * 16 + jl);
        int s = k * C4H + colH;
        g_wt2[jj] = whh_mu[s] + softplusf_(whh_rho[s]) * eps_hh[s];
    } else if (i < N3) {
        int jj = i - N2;
        g_bias[jj] = b_mu[jj] + softplusf_(b_rho[jj]) * eps_b[jj];
    } else if (i < N4) {
        g_bar[i - N3] = 0u;
    }
}

// ---------------- x transpose: x[b][t][d] -> xT[bg][t][k][b8] ----------------
__global__ __launch_bounds__(256) void xpose_kernel(const float* __restrict__ x) {
    int idx = blockIdx.x * 256 + threadIdx.x;      // 4*1024*128*8 = 4194304
    int b8 = idx & 7;
    int k4 = (idx >> 3) & 127;
    int t  = (idx >> 10) & 1023;
    int bg = idx >> 20;
    float4 v = *(const float4*)&x[((size_t)(bg * 8 + b8) * 1024 + t) * 512 + k4 * 4];
    size_t base = ((size_t)(bg * 1024 + t) * 512) * 8;
    g_xt[base + (size_t)(k4 * 4 + 0) * 8 + b8] = v.x;
    g_xt[base + (size_t)(k4 * 4 + 1) * 8 + b8] = v.y;
    g_xt[base + (size_t)(k4 * 4 + 2) * 8 + b8] = v.z;
    g_xt[base + (size_t)(k4 * 4 + 3) * 8 + b8] = v.w;
}

// ---------------- fused persistent GRU scan + input GEMM ----------------
#define SK_W 52

struct ScanSmem {
    float w[512 * SK_W];          // 106496 B
    float h[512 * 8];             // 16384 B, [k][b8]
    float x[2][512 * 8];          // 32768 B, [k][b8]
    float part[8 * 16 * 3 * 10];  // 15360 B (scan partials)
    float part2[8 * 16 * 3 * 10]; // 15360 B (gemm partials)
};

__global__ __launch_bounds__(256, 1) void scan_kernel(const float* __restrict__ h0,
                                                      float* __restrict__ out,
                                                      int write_last) {
    extern __shared__ float smem_raw[];
    ScanSmem* S = (ScanSmem*)smem_raw;

    const int tid = threadIdx.x;
    const int bg = blockIdx.x >> 5;
    const int jg = blockIdx.x & 31;
    const int j = tid & 15;
    const int ks = tid >> 4;
    const int k0 = ks * 32;
    const int wid = tid >> 5;
    const int lane = tid & 31;
    const int fb = tid >> 4;       // final-stage b (tid<128)
    const int jgl = jg * 16 + j;

    // ---- w_hh columns into smem ----
    {
        const float* wb = g_wt2 + (size_t)jg * 24576;
        for (int q = tid; q < 6144; q += 256) {
            int k = q / 12, c4 = (q % 12) * 4;
            float4 v = *(const float4*)&wb[k * 48 + c4];
            *(float4*)&S->w[k * SK_W + c4] = v;
        }
    }
    // ---- w_ih slice into registers (constant for whole scan) ----
    float wr_ih[32], wz_ih[32], wn_ih[32];
    {
        const float* p = g_wih + (size_t)k0 * NG + (jg * 16 + j);
#pragma unroll
        for (int kk = 0; kk < 32; kk++) {
            wr_ih[kk] = __ldg(&p[kk * NG]);
            wz_ih[kk] = __ldg(&p[kk * NG + 512]);
            wn_ih[kk] = __ldg(&p[kk * NG + 1024]);
        }
    }
    float b_r = 0.f, b_z = 0.f, b_n = 0.f, b_hn = 0.f;
    if (tid < 128) {
        b_r  = g_bias[jgl];
        b_z  = g_bias[512 + jgl];
        b_n  = g_bias[1024 + jgl];
        b_hn = g_bias[1536 + jgl];
    }

    // ---- stage x(0) into xbuf[1] (temp) ----
    {
        const float* xsrc = g_xt + ((size_t)(bg * 1024 + 0) * 512) * 8;
#pragma unroll
        for (int i = 0; i < 4; i++) {
            int q = (tid + 256 * i) << 2;
            float4 v = __ldg((const float4*)&xsrc[q]);
            *(float4*)&S->x[1][q] = v;
        }
    }
    __syncthreads();

    // ---- compute xg(0) into regs ----
    float xr = 0.f, xz = 0.f, xn = 0.f;
    {
        ull acc[3][4];
#pragma unroll
        for (int g = 0; g < 3; g++)
#pragma unroll
            for (int p = 0; p < 4; p++) acc[g][p] = 0ull;
        const float* xp = &S->x[1][0];
#pragma unroll
        for (int kk = 0; kk < 32; kk++) {
            int k = k0 + kk;
            ulonglong2 hA = *(const ulonglong2*)&xp[k * 8];
            ulonglong2 hB = *(const ulonglong2*)&xp[k * 8 + 4];
            ull wr = pack2(wr_ih[kk]);
            ull wz = pack2(wz_ih[kk]);
            ull wn = pack2(wn_ih[kk]);
            fma2(acc[0][0], hA.x, wr); fma2(acc[0][1], hA.y, wr);
            fma2(acc[0][2], hB.x, wr); fma2(acc[0][3], hB.y, wr);
            fma2(acc[1][0], hA.x, wz); fma2(acc[1][1], hA.y, wz);
            fma2(acc[1][2], hB.x, wz); fma2(acc[1][3], hB.y, wz);
            fma2(acc[2][0], hA.x, wn); fma2(acc[2][1], hA.y, wn);
            fma2(acc[2][2], hB.x, wn); fma2(acc[2][3], hB.y, wn);
        }
#pragma unroll
        for (int g = 0; g < 3; g++)
#pragma unroll
            for (int p = 0; p < 4; p++) {
                ull o = __shfl_xor_sync(0xffffffffu, acc[g][p], 16);
                acc[g][p] = add2(acc[g][p], o);
            }
        if (lane < 16) {
#pragma unroll
            for (int g = 0; g < 3; g++)
#pragma unroll
                for (int p = 0; p < 4; p++)
                    *(ull*)&S->part[(((wid * 16 + j) * 3 + g) * 5 + p) * 2] = acc[g][p];
        }
        __syncthreads();
        if (tid < 128) {
#pragma unroll
            for (int w = 0; w < 8; w++) {
                const float* pp = &S->part[((w * 16 + j) * 3) * 10 + fb];
                xr += pp[0];
                xz += pp[10];
                xn += pp[20];
            }
        }
    }

    // ---- stage x(1) into xbuf[0]; load h0 into S->h ----
    {
        const float* xsrc = g_xt + ((size_t)(bg * 1024 + 1) * 512) * 8;
#pragma unroll
        for (int i = 0; i < 4; i++) {
            int q = (tid + 256 * i) << 2;
            float4 v = __ldg((const float4*)&xsrc[q]);
            *(float4*)&S->x[0][q] = v;
        }
        const float* hsrc = h0 + (size_t)bg * 8 * 512;
        for (int q = tid; q < 1024; q += 256) {
            int b8 = q >> 7, kq = (q & 127) << 2;
            float4 v = *(const float4*)&hsrc[b8 * 512 + kq];
            S->h[(kq + 0) * 8 + b8] = v.x;
            S->h[(kq + 1) * 8 + b8] = v.y;
            S->h[(kq + 2) * 8 + b8] = v.z;
            S->h[(kq + 3) * 8 + b8] = v.w;
        }
    }
    __syncthreads();

    for (int t = 0; t < Tlen; t++) {
        const bool more = (t < Tlen - 1);
        const bool havex = (t + 2 < Tlen);
        // issue LDG for x(t+2) early — upper 128 threads only (they stage it)
        float4 x4[8];
        if (havex && tid >= 128) {
            const float* xsrc = g_xt + ((size_t)(bg * 1024 + t + 2) * 512) * 8;
#pragma unroll
            for (int i = 0; i < 8; i++)
                x4[i] = __ldg((const float4*)&xsrc[((tid - 128) + 128 * i) << 2]);
        }

        // ---- scan dots: h(t) @ w_hh ----
        {
            ull acc[3][4];
#pragma unroll
            for (int g = 0; g < 3; g++)
#pragma unroll
                for (int p = 0; p < 4; p++) acc[g][p] = 0ull;
#pragma unroll 4
            for (int kk = 0; kk < 32; kk++) {
                int k = k0 + kk;
                const float* hp = &S->h[k * 8];
                ulonglong2 hA = *(const ulonglong2*)(hp);
                ulonglong2 hB = *(const ulonglong2*)(hp + 4);
                const float* wp = &S->w[k * SK_W];
                ull wr = pack2(wp[j]);
                ull wz = pack2(wp[16 + j]);
                ull wn = pack2(wp[32 + j]);
                fma2(acc[0][0], hA.x, wr); fma2(acc[0][1], hA.y, wr);
                fma2(acc[0][2], hB.x, wr); fma2(acc[0][3], hB.y, wr);
                fma2(acc[1][0], hA.x, wz); fma2(acc[1][1], hA.y, wz);
                fma2(acc[1][2], hB.x, wz); fma2(acc[1][3], hB.y, wz);
                fma2(acc[2][0], hA.x, wn); fma2(acc[2][1], hA.y, wn);
                fma2(acc[2][2], hB.x, wn); fma2(acc[2][3], hB.y, wn);
            }
#pragma unroll
            for (int g = 0; g < 3; g++)
#pragma unroll
                for (int p = 0; p < 4; p++) {
                    ull o = __shfl_xor_sync(0xffffffffu, acc[g][p], 16);
                    acc[g][p] = add2(acc[g][p], o);
                }
            if (lane < 16) {
#pragma unroll
                for (int g = 0; g < 3; g++)
#pragma unroll
                    for (int p = 0; p < 4; p++)
                        *(ull*)&S->part[(((wid * 16 + j) * 3 + g) * 5 + p) * 2] = acc[g][p];
            }
        }
        __syncthreads();   // A

        // ---- final: gates (lower half) || x(t+2) staging (upper half) ----
        float hnew = 0.f;
        if (tid < 128) {
            float sr = 0.f, sz = 0.f, sn = 0.f;
#pragma unroll
            for (int w = 0; w < 8; w++) {
                const float* pp = &S->part[((w * 16 + j) * 3) * 10 + fb];
                sr += pp[0];
                sz += pp[10];
                sn += pp[20];
            }
            float r = 1.f / (1.f + __expf(-(sr + xr + b_r)));
            float z = 1.f / (1.f + __expf(-(sz + xz + b_z)));
            float n = tanhf(xn + b_n + r * (sn + b_hn));
            float hprev = S->h[jgl * 8 + fb];
            hnew = (1.f - z) * n + z * hprev;
            if (more) g_ht[(t + 1) & 1][bg][jgl * 8 + fb] = hnew;
        } else if (havex) {
#pragma unroll
            for (int i = 0; i < 8; i++)
                *(float4*)&S->x[(t + 1) & 1][((tid - 128) + 128 * i) << 2] = x4[i];
        }
        __syncthreads();   // B: h stores + staging ordered before arrive

        if (more) {
            if (tid == 0) {
                unsigned* bp = &g_bar[bg * Tlen + t];
                asm volatile("red.release.gpu.global.add.u32 [%0], %1;"
                             :: "l"(bp), "r"(1u) : "memory");
            }

            // ---- barrier shadow: gemm dots for xg(t+1) ----
            {
                ull acc2[3][4];
#pragma unroll
                for (int g = 0; g < 3; g++)
#pragma unroll
                    for (int p = 0; p < 4; p++) acc2[g][p] = 0ull;
                const float* xp = &S->x[t & 1][0];
#pragma unroll
                for (int kk = 0; kk < 32; kk++) {
                    int k = k0 + kk;
                    ulonglong2 hA = *(const ulonglong2*)&xp[k * 8];
                    ulonglong2 hB = *(const ulonglong2*)&xp[k * 8 + 4];
                    ull wr = pack2(wr_ih[kk]);
                    ull wz = pack2(wz_ih[kk]);
                    ull wn = pack2(wn_ih[kk]);
                    fma2(acc2[0][0], hA.x, wr); fma2(acc2[0][1], hA.y, wr);
                    fma2(acc2[0][2], hB.x, wr); fma2(acc2[0][3], hB.y, wr);
                    fma2(acc2[1][0], hA.x, wz); fma2(acc2[1][1], hA.y, wz);
                    fma2(acc2[1][2], hB.x, wz); fma2(acc2[1][3], hB.y, wz);
                    fma2(acc2[2][0], hA.x, wn); fma2(acc2[2][1], hA.y, wn);
                    fma2(acc2[2][2], hB.x, wn); fma2(acc2[2][3], hB.y, wn);
                }
#pragma unroll
                for (int g = 0; g < 3; g++)
#pragma unroll
                    for (int p = 0; p < 4; p++) {
                        ull o = __shfl_xor_sync(0xffffffffu, acc2[g][p], 16);
                        acc2[g][p] = add2(acc2[g][p], o);
                    }
                if (lane < 16) {
#pragma unroll
                    for (int g = 0; g < 3; g++)
#pragma unroll
                        for (int p = 0; p < 4; p++)
                            *(ull*)&S->part2[(((wid * 16 + j) * 3 + g) * 5 + p) * 2] = acc2[g][p];
                }
            }
            __syncthreads();   // C

            // ---- all-lane acquire poll (per-warp release from barrier) ----
            {
                unsigned* bp = &g_bar[bg * Tlen + t];
                unsigned vv;
                do {
                    asm volatile("ld.acquire.gpu.global.u32 %0, [%1];"
                                 : "=r"(vv) : "l"(bp) : "memory");
                } while (vv < 32u);
            }
            // ---- issue h(t+1) pull immediately; overlap with out STG + gemm reduce ----
            const float* hsrc = &g_ht[(t + 1) & 1][bg][0];
            float4 hv[4];
#pragma unroll
            for (int i = 0; i < 4; i++)
                hv[i] = __ldcg((const float4*)&hsrc[(tid + 256 * i) << 2]);

            if (tid < 128) {
                out[((size_t)(bg * 8 + fb) * 1024 + t) * 512 + jgl] = hnew;
                xr = 0.f; xz = 0.f; xn = 0.f;
#pragma unroll
                for (int w = 0; w < 8; w++) {
                    const float* pp = &S->part2[((w * 16 + j) * 3) * 10 + fb];
                    xr += pp[0];
                    xz += pp[10];
                    xn += pp[20];
                }
            }
#pragma unroll
            for (int i = 0; i < 4; i++)
                *(float4*)&S->h[(tid + 256 * i) << 2] = hv[i];
            __syncthreads();   // E (merged D+E)
        } else {
            if (tid < 128) {
                out[((size_t)(bg * 8 + fb) * 1024 + t) * 512 + jgl] = hnew;
                if (write_last)
                    out[(size_t)Bsz * Tlen * Hh + (bg * 8 + fb) * 512 + jgl] = hnew;
            }
        }
    }
}

// ---------------- launch ----------------
extern "C" void kernel_launch(void* const* d_in, const int* in_sizes, int n_in,
                              void* d_out, int out_size) {
    const float* x       = (const float*)d_in[0];
    const float* h0      = (const float*)d_in[1];
    const float* wih_mu  = (const float*)d_in[2];
    const float* wih_rho = (const float*)d_in[3];
    const float* whh_mu  = (const float*)d_in[4];
    const float* whh_rho = (const float*)d_in[5];
    const float* b_mu    = (const float*)d_in[6];
    const float* b_rho   = (const float*)d_in[7];
    const float* eps_ih  = (const float*)d_in[8];
    const float* eps_hh  = (const float*)d_in[9];
    const float* eps_b   = (const float*)d_in[10];
    float* out = (float*)d_out;

    {
        int total = Dd * NG + 32 * 512 * 48 + C4H + 4 * Tlen;
        int blocks = (total + 255) / 256;
        sample_all_kernel<<<blocks, 256>>>(wih_mu, wih_rho, eps_ih,
                                           whh_mu, whh_rho, eps_hh,
                                           b_mu, b_rho, eps_b);
    }
    {
        int threads = 4 * 1024 * 128 * 8;   // 4194304
        xpose_kernel<<<threads / 256, 256>>>(x);
    }
    {
        int smem = (int)sizeof(ScanSmem);
        cudaFuncSetAttribute(scan_kernel, cudaFuncAttributeMaxDynamicSharedMemorySize, smem);
        int write_last = (out_size >= Bsz * Tlen * Hh + Bsz * Hh) ? 1 : 0;
        scan_kernel<<<128, 256, smem>>>(h0, out, write_last);
    }
}

// round 12
// speedup vs baseline: 1.9310x; 1.0569x over previous
#include <cuda_runtime.h>
#include <math.h>

// Problem constants
#define Bsz  32
#define Tlen 1024
#define Dd   512
#define Hh   512
#define NG   1536   // 3*H
#define C4H  2048   // 4*H

// -------- device scratch --------
__device__ float g_wih[Dd * NG];                 // sampled w_ih[:, :3H], [d][c]
__device__ float g_wt2[32 * 512 * 48];           // scan weights [jg][k][c], c = g*16+jl
__device__ float g_bias[C4H];
__device__ float g_xt[(size_t)4 * Tlen * 512 * 8]; // x transposed: [bg][t][k][b8]
__device__ float g_ht[2][4][512 * 8];            // ping-pong hidden, transposed [bg][k][b8]
__device__ unsigned g_bar[4 * Tlen];             // per-batch-group barrier counters

__device__ __forceinline__ float softplusf_(float x) {
    return x > 20.f ? x : log1pf(__expf(x));
}

typedef unsigned long long ull;
__device__ __forceinline__ ull pack2(float x) {
    ull d; unsigned u = __float_as_uint(x);
    asm("mov.b64 %0, {%1, %1};" : "=l"(d) : "r"(u));
    return d;
}
__device__ __forceinline__ void fma2(ull& d, ull a, ull b) {
    asm("fma.rn.f32x2 %0, %1, %2, %0;" : "+l"(d) : "l"(a), "l"(b));
}
__device__ __forceinline__ ull add2(ull a, ull b) {
    ull d;
    asm("add.rn.f32x2 %0, %1, %2;" : "=l"(d) : "l"(a), "l"(b));
    return d;
}

// ---------------- prologue: sample weights + reset barriers ----------------
__global__ void sample_all_kernel(const float* __restrict__ wih_mu, const float* __restrict__ wih_rho,
                                  const float* __restrict__ eps_ih,
                                  const float* __restrict__ whh_mu, const float* __restrict__ whh_rho,
                                  const float* __restrict__ eps_hh,
                                  const float* __restrict__ b_mu, const float* __restrict__ b_rho,
                                  const float* __restrict__ eps_b) {
    int i = blockIdx.x * blockDim.x + threadIdx.x;
    const int N1 = Dd * NG;
    const int N2 = N1 + 32 * 512 * 48;
    const int N3 = N2 + C4H;
    const int N4 = N3 + 4 * Tlen;
    if (i < N1) {
        int d = i / NG, c = i % NG;
        int s = d * C4H + c;
        g_wih[i] = wih_mu[s] + softplusf_(wih_rho[s]) * eps_ih[s];
    } else if (i < N2) {
        int jj = i - N1;
        int jg = jj / 24576;
        int r = jj % 24576;
        int k = r / 48;
        int c = r % 48;
        int g = c >> 4;
        int jl = c & 15;
        int colH = (g < 2) ? (g * 512 + jg * 16 + jl) : (1536 + jg * 16 + jl);
        int s = k * C4H + colH;
        g_wt2[jj] = whh_mu[s] + softplusf_(whh_rho[s]) * eps_hh[s];
    } else if (i < N3) {
        int jj = i - N2;
        g_bias[jj] = b_mu[jj] + softplusf_(b_rho[jj]) * eps_b[jj];
    } else if (i < N4) {
        g_bar[i - N3] = 0u;
    }
}

// ---------------- x transpose: x[b][t][d] -> xT[bg][t][k][b8] ----------------
__global__ __launch_bounds__(256) void xpose_kernel(const float* __restrict__ x) {
    int idx = blockIdx.x * 256 + threadIdx.x;      // 4*1024*128*8 = 4194304
    int b8 = idx & 7;
    int k4 = (idx >> 3) & 127;
    int t  = (idx >> 10) & 1023;
    int bg = idx >> 20;
    float4 v = *(const float4*)&x[((size_t)(bg * 8 + b8) * 1024 + t) * 512 + k4 * 4];
    size_t base = ((size_t)(bg * 1024 + t) * 512) * 8;
    g_xt[base + (size_t)(k4 * 4 + 0) * 8 + b8] = v.x;
    g_xt[base + (size_t)(k4 * 4 + 1) * 8 + b8] = v.y;
    g_xt[base + (size_t)(k4 * 4 + 2) * 8 + b8] = v.z;
    g_xt[base + (size_t)(k4 * 4 + 3) * 8 + b8] = v.w;
}

// ---------------- fused persistent GRU scan + input GEMM ----------------
#define SK_W 52

struct ScanSmem {
    float w[512 * SK_W];          // 106496 B
    float h[512 * 8];             // 16384 B, [k][b8]
    float x[2][512 * 8];          // 32768 B, [k][b8]
    float part[8 * 16 * 3 * 10];  // 15360 B (scan partials)
    float part2[8 * 16 * 3 * 10]; // 15360 B (gemm partials)
};

__global__ __launch_bounds__(256, 1) void scan_kernel(const float* __restrict__ h0,
                                                      float* __restrict__ out,
                                                      int write_last) {
    extern __shared__ float smem_raw[];
    ScanSmem* S = (ScanSmem*)smem_raw;

    const int tid = threadIdx.x;
    const int bg = blockIdx.x >> 5;
    const int jg = blockIdx.x & 31;
    const int j = tid & 15;
    const int ks = tid >> 4;
    const int k0 = ks * 32;
    const int wid = tid >> 5;
    const int lane = tid & 31;
    const int fb = tid >> 4;       // final-stage b (tid<128)
    const int jgl = jg * 16 + j;

    // ---- w_hh columns into smem ----
    {
        const float* wb = g_wt2 + (size_t)jg * 24576;
        for (int q = tid; q < 6144; q += 256) {
            int k = q / 12, c4 = (q % 12) * 4;
            float4 v = *(const float4*)&wb[k * 48 + c4];
            *(float4*)&S->w[k * SK_W + c4] = v;
        }
    }
    // ---- w_ih slice into registers (constant for whole scan) ----
    float wr_ih[32], wz_ih[32], wn_ih[32];
    {
        const float* p = g_wih + (size_t)k0 * NG + (jg * 16 + j);
#pragma unroll
        for (int kk = 0; kk < 32; kk++) {
            wr_ih[kk] = __ldg(&p[kk * NG]);
            wz_ih[kk] = __ldg(&p[kk * NG + 512]);
            wn_ih[kk] = __ldg(&p[kk * NG + 1024]);
        }
    }
    float b_r = 0.f, b_z = 0.f, b_n = 0.f, b_hn = 0.f;
    if (tid < 128) {
        b_r  = g_bias[jgl];
        b_z  = g_bias[512 + jgl];
        b_n  = g_bias[1024 + jgl];
        b_hn = g_bias[1536 + jgl];
    }

    // ---- stage x(0) into xbuf[1] (temp) ----
    {
        const float* xsrc = g_xt + ((size_t)(bg * 1024 + 0) * 512) * 8;
#pragma unroll
        for (int i = 0; i < 4; i++) {
            int q = (tid + 256 * i) << 2;
            float4 v = __ldg((const float4*)&xsrc[q]);
            *(float4*)&S->x[1][q] = v;
        }
    }
    __syncthreads();

    // ---- compute xg(0) into regs ----
    float xr = 0.f, xz = 0.f, xn = 0.f;
    {
        ull acc[3][4];
#pragma unroll
        for (int g = 0; g < 3; g++)
#pragma unroll
            for (int p = 0; p < 4; p++) acc[g][p] = 0ull;
        const float* xp = &S->x[1][0];
#pragma unroll
        for (int kk = 0; kk < 32; kk++) {
            int k = k0 + kk;
            ulonglong2 hA = *(const ulonglong2*)&xp[k * 8];
            ulonglong2 hB = *(const ulonglong2*)&xp[k * 8 + 4];
            ull wr = pack2(wr_ih[kk]);
            ull wz = pack2(wz_ih[kk]);
            ull wn = pack2(wn_ih[kk]);
            fma2(acc[0][0], hA.x, wr); fma2(acc[0][1], hA.y, wr);
            fma2(acc[0][2], hB.x, wr); fma2(acc[0][3], hB.y, wr);
            fma2(acc[1][0], hA.x, wz); fma2(acc[1][1], hA.y, wz);
            fma2(acc[1][2], hB.x, wz); fma2(acc[1][3], hB.y, wz);
            fma2(acc[2][0], hA.x, wn); fma2(acc[2][1], hA.y, wn);
            fma2(acc[2][2], hB.x, wn); fma2(acc[2][3], hB.y, wn);
        }
#pragma unroll
        for (int g = 0; g < 3; g++)
#pragma unroll
            for (int p = 0; p < 4; p++) {
                ull o = __shfl_xor_sync(0xffffffffu, acc[g][p], 16);
                acc[g][p] = add2(acc[g][p], o);
            }
        if (lane < 16) {
#pragma unroll
            for (int g = 0; g < 3; g++)
#pragma unroll
                for (int p = 0; p < 4; p++)
                    *(ull*)&S->part[(((wid * 16 + j) * 3 + g) * 5 + p) * 2] = acc[g][p];
        }
        __syncthreads();
        if (tid < 128) {
#pragma unroll
            for (int w = 0; w < 8; w++) {
                const float* pp = &S->part[((w * 16 + j) * 3) * 10 + fb];
                xr += pp[0];
                xz += pp[10];
                xn += pp[20];
            }
        }
    }

    // ---- stage x(1) into xbuf[0]; load h0 into S->h ----
    {
        const float* xsrc = g_xt + ((size_t)(bg * 1024 + 1) * 512) * 8;
#pragma unroll
        for (int i = 0; i < 4; i++) {
            int q = (tid + 256 * i) << 2;
            float4 v = __ldg((const float4*)&xsrc[q]);
            *(float4*)&S->x[0][q] = v;
        }
        const float* hsrc = h0 + (size_t)bg * 8 * 512;
        for (int q = tid; q < 1024; q += 256) {
            int b8 = q >> 7, kq = (q & 127) << 2;
            float4 v = *(const float4*)&hsrc[b8 * 512 + kq];
            S->h[(kq + 0) * 8 + b8] = v.x;
            S->h[(kq + 1) * 8 + b8] = v.y;
            S->h[(kq + 2) * 8 + b8] = v.z;
            S->h[(kq + 3) * 8 + b8] = v.w;
        }
    }
    __syncthreads();

    for (int t = 0; t < Tlen; t++) {
        const bool more = (t < Tlen - 1);
        const bool havex = (t + 2 < Tlen);
        // issue LDG for x(t+2) early — upper 128 threads only (they stage it)
        float4 x4[8];
        if (havex && tid >= 128) {
            const float* xsrc = g_xt + ((size_t)(bg * 1024 + t + 2) * 512) * 8;
#pragma unroll
            for (int i = 0; i < 8; i++)
                x4[i] = __ldg((const float4*)&xsrc[((tid - 128) + 128 * i) << 2]);
        }

        // ---- scan dots: h(t) @ w_hh (reads only k in [64*wid, 64*wid+64)) ----
        {
            ull acc[3][4];
#pragma unroll
            for (int g = 0; g < 3; g++)
#pragma unroll
                for (int p = 0; p < 4; p++) acc[g][p] = 0ull;
#pragma unroll 4
            for (int kk = 0; kk < 32; kk++) {
                int k = k0 + kk;
                const float* hp = &S->h[k * 8];
                ulonglong2 hA = *(const ulonglong2*)(hp);
                ulonglong2 hB = *(const ulonglong2*)(hp + 4);
                const float* wp = &S->w[k * SK_W];
                ull wr = pack2(wp[j]);
                ull wz = pack2(wp[16 + j]);
                ull wn = pack2(wp[32 + j]);
                fma2(acc[0][0], hA.x, wr); fma2(acc[0][1], hA.y, wr);
                fma2(acc[0][2], hB.x, wr); fma2(acc[0][3], hB.y, wr);
                fma2(acc[1][0], hA.x, wz); fma2(acc[1][1], hA.y, wz);
                fma2(acc[1][2], hB.x, wz); fma2(acc[1][3], hB.y, wz);
                fma2(acc[2][0], hA.x, wn); fma2(acc[2][1], hA.y, wn);
                fma2(acc[2][2], hB.x, wn); fma2(acc[2][3], hB.y, wn);
            }
#pragma unroll
            for (int g = 0; g < 3; g++)
#pragma unroll
                for (int p = 0; p < 4; p++) {
                    ull o = __shfl_xor_sync(0xffffffffu, acc[g][p], 16);
                    acc[g][p] = add2(acc[g][p], o);
                }
            if (lane < 16) {
#pragma unroll
                for (int g = 0; g < 3; g++)
#pragma unroll
                    for (int p = 0; p < 4; p++)
                        *(ull*)&S->part[(((wid * 16 + j) * 3 + g) * 5 + p) * 2] = acc[g][p];
            }
        }
        __syncthreads();   // A

        // ---- final: gates (lower half) || x(t+2) staging (upper half) ----
        float hnew = 0.f;
        if (tid < 128) {
            float sr = 0.f, sz = 0.f, sn = 0.f;
#pragma unroll
            for (int w = 0; w < 8; w++) {
                const float* pp = &S->part[((w * 16 + j) * 3) * 10 + fb];
                sr += pp[0];
                sz += pp[10];
                sn += pp[20];
            }
            float r = 1.f / (1.f + __expf(-(sr + xr + b_r)));
            float z = 1.f / (1.f + __expf(-(sz + xz + b_z)));
            float n = tanhf(xn + b_n + r * (sn + b_hn));
            float hprev = S->h[jgl * 8 + fb];
            hnew = (1.f - z) * n + z * hprev;
            if (more) g_ht[(t + 1) & 1][bg][jgl * 8 + fb] = hnew;
        } else if (havex) {
#pragma unroll
            for (int i = 0; i < 8; i++)
                *(float4*)&S->x[(t + 1) & 1][((tid - 128) + 128 * i) << 2] = x4[i];
        }
        __syncthreads();   // B: h stores + staging ordered before arrive

        if (more) {
            if (tid == 0) {
                unsigned* bp = &g_bar[bg * Tlen + t];
                asm volatile("red.release.gpu.global.add.u32 [%0], %1;"
                             :: "l"(bp), "r"(1u) : "memory");
            }

            // ---- barrier shadow: gemm dots for xg(t+1) ----
            {
                ull acc2[3][4];
#pragma unroll
                for (int g = 0; g < 3; g++)
#pragma unroll
                    for (int p = 0; p < 4; p++) acc2[g][p] = 0ull;
                const float* xp = &S->x[t & 1][0];
#pragma unroll
                for (int kk = 0; kk < 32; kk++) {
                    int k = k0 + kk;
                    ulonglong2 hA = *(const ulonglong2*)&xp[k * 8];
                    ulonglong2 hB = *(const ulonglong2*)&xp[k * 8 + 4];
                    ull wr = pack2(wr_ih[kk]);
                    ull wz = pack2(wz_ih[kk]);
                    ull wn = pack2(wn_ih[kk]);
                    fma2(acc2[0][0], hA.x, wr); fma2(acc2[0][1], hA.y, wr);
                    fma2(acc2[0][2], hB.x, wr); fma2(acc2[0][3], hB.y, wr);
                    fma2(acc2[1][0], hA.x, wz); fma2(acc2[1][1], hA.y, wz);
                    fma2(acc2[1][2], hB.x, wz); fma2(acc2[1][3], hB.y, wz);
                    fma2(acc2[2][0], hA.x, wn); fma2(acc2[2][1], hA.y, wn);
                    fma2(acc2[2][2], hB.x, wn); fma2(acc2[2][3], hB.y, wn);
                }
#pragma unroll
                for (int g = 0; g < 3; g++)
#pragma unroll
                    for (int p = 0; p < 4; p++) {
                        ull o = __shfl_xor_sync(0xffffffffu, acc2[g][p], 16);
                        acc2[g][p] = add2(acc2[g][p], o);
                    }
                if (lane < 16) {
#pragma unroll
                    for (int g = 0; g < 3; g++)
#pragma unroll
                        for (int p = 0; p < 4; p++)
                            *(ull*)&S->part2[(((wid * 16 + j) * 3 + g) * 5 + p) * 2] = acc2[g][p];
                }
            }
            __syncthreads();   // C (orders part2 STS + last S->h reads)

            // ---- all-lane acquire poll; then PER-WARP h pull (no CTA sync) ----
            {
                unsigned* bp = &g_bar[bg * Tlen + t];
                unsigned vv;
                do {
                    asm volatile("ld.acquire.gpu.global.u32 %0, [%1];"
                                 : "=r"(vv) : "l"(bp) : "memory");
                } while (vv < 32u);
            }
            // each warp pulls exactly the k-chunk its scan dots read: k in [64*wid, 64*wid+64)
            {
                const float* hsrc = &g_ht[(t + 1) & 1][bg][0];
                const int hb = wid * 512 + lane * 4;   // lane-consecutive 16B -> conflict-free
                float4 hv[4];
#pragma unroll
                for (int i = 0; i < 4; i++)
                    hv[i] = __ldcg((const float4*)&hsrc[hb + 128 * i]);

                // overlap LDG latency: out STG + gemm reduce
                if (tid < 128) {
                    out[((size_t)(bg * 8 + fb) * 1024 + t) * 512 + jgl] = hnew;
                    xr = 0.f; xz = 0.f; xn = 0.f;
#pragma unroll
                    for (int w = 0; w < 8; w++) {
                        const float* pp = &S->part2[((w * 16 + j) * 3) * 10 + fb];
                        xr += pp[0];
                        xz += pp[10];
                        xn += pp[20];
                    }
                }
#pragma unroll
                for (int i = 0; i < 4; i++)
                    *(float4*)&S->h[hb + 128 * i] = hv[i];
                __syncwarp();
            }
            // next iteration's scan dots read only this warp's staged chunk
        } else {
            if (tid < 128) {
                out[((size_t)(bg * 8 + fb) * 1024 + t) * 512 + jgl] = hnew;
                if (write_last)
                    out[(size_t)Bsz * Tlen * Hh + (bg * 8 + fb) * 512 + jgl] = hnew;
            }
        }
    }
}

// ---------------- launch ----------------
extern "C" void kernel_launch(void* const* d_in, const int* in_sizes, int n_in,
                              void* d_out, int out_size) {
    const float* x       = (const float*)d_in[0];
    const float* h0      = (const float*)d_in[1];
    const float* wih_mu  = (const float*)d_in[2];
    const float* wih_rho = (const float*)d_in[3];
    const float* whh_mu  = (const float*)d_in[4];
    const float* whh_rho = (const float*)d_in[5];
    const float* b_mu    = (const float*)d_in[6];
    const float* b_rho   = (const float*)d_in[7];
    const float* eps_ih  = (const float*)d_in[8];
    const float* eps_hh  = (const float*)d_in[9];
    const float* eps_b   = (const float*)d_in[10];
    float* out = (float*)d_out;

    {
        int total = Dd * NG + 32 * 512 * 48 + C4H + 4 * Tlen;
        int blocks = (total + 255) / 256;
        sample_all_kernel<<<blocks, 256>>>(wih_mu, wih_rho, eps_ih,
                                           whh_mu, whh_rho, eps_hh,
                                           b_mu, b_rho, eps_b);
    }
    {
        int threads = 4 * 1024 * 128 * 8;   // 4194304
        xpose_kernel<<<threads / 256, 256>>>(x);
    }
    {
        int smem = (int)sizeof(ScanSmem);
        cudaFuncSetAttribute(scan_kernel, cudaFuncAttributeMaxDynamicSharedMemorySize, smem);
        int write_last = (out_size >= Bsz * Tlen * Hh + Bsz * Hh) ? 1 : 0;
        scan_kernel<<<128, 256, smem>>>(h0, out, write_last);
    }
}